// round 12
// baseline (speedup 1.0000x reference)
#include <cuda_runtime.h>
#include <cstdint>
#include <math.h>

#define Bnum 32
#define Tnum 2048
#define Hnum 512
#define CHUNK 32                    // t-rows per energy block
#define STG_ROWS 8                  // rows per cp.async stage
#define NSTG (CHUNK / STG_ROWS)     // 4 stages
#define NCHUNK (Tnum / CHUNK)       // 64 chunks per b
#define ETHR 256                    // energy block threads (8 warps)
#define ROW4 (Hnum / 4)             // 128 float4 per row

// Scratch (static device arrays — allocation-free per harness rules)
__device__ __align__(16) float g_has[Bnum * Hnum];     // ha (unscaled)
__device__ __align__(16) float g_p[Bnum * Tnum];       // unnormalized numerators
__device__ __align__(16) float g_psum[Bnum * NCHUNK];  // per-(b,chunk) partials
__device__ unsigned g_done[Bnum];                      // zero-init; reset each use

__device__ __forceinline__ float ex2a(float x) {
    float y; asm("ex2.approx.f32 %0, %1;" : "=f"(y) : "f"(x)); return y;
}
__device__ __forceinline__ float tanha(float x) {
    float y; asm("tanh.approx.f32 %0, %1;" : "=f"(y) : "f"(x)); return y;
}
__device__ __forceinline__ void cp16(void* smem_dst, const void* gsrc) {
    unsigned int sa = (unsigned int)__cvta_generic_to_shared(smem_dst);
    asm volatile("cp.async.cg.shared.global [%0], [%1], 16;" :: "r"(sa), "l"(gsrc));
}

#define LOG2E 1.4426950408889634f

// ---------------------------------------------------------------------------
// Kernel A: ha[b,h] = sum_k mean_L(hidden)[b,k]*Wh[h,k] + bh[h].
// ---------------------------------------------------------------------------
__global__ __launch_bounds__(256) void proj_kernel(
    const float* __restrict__ hidden,
    const float* __restrict__ Wh,
    const float* __restrict__ bh)
{
    const int h0 = blockIdx.x * 8;
    __shared__ float s_w[8 * Hnum];   // 16KB
    {
        const float4* __restrict__ w4 = (const float4*)(Wh + (size_t)h0 * Hnum);
        for (int i = threadIdx.x; i < 8 * Hnum / 4; i += 256)
            ((float4*)s_w)[i] = w4[i];
    }
    __syncthreads();

    const int warp = threadIdx.x >> 5;
    const int lane = threadIdx.x & 31;
    const int b0 = warp * 4;
    const float* __restrict__ hA = hidden;                 // layer 0
    const float* __restrict__ hB = hidden + Bnum * Hnum;   // layer 1

    float acc[8][4];
    #pragma unroll
    for (int h = 0; h < 8; h++)
        #pragma unroll
        for (int j = 0; j < 4; j++) acc[h][j] = 0.f;

    #pragma unroll
    for (int k = lane; k < Hnum; k += 32) {
        float v0 = 0.5f * (hA[(b0 + 0) * Hnum + k] + hB[(b0 + 0) * Hnum + k]);
        float v1 = 0.5f * (hA[(b0 + 1) * Hnum + k] + hB[(b0 + 1) * Hnum + k]);
        float v2 = 0.5f * (hA[(b0 + 2) * Hnum + k] + hB[(b0 + 2) * Hnum + k]);
        float v3 = 0.5f * (hA[(b0 + 3) * Hnum + k] + hB[(b0 + 3) * Hnum + k]);
        #pragma unroll
        for (int h = 0; h < 8; h++) {
            float w = s_w[h * Hnum + k];
            acc[h][0] = fmaf(v0, w, acc[h][0]);
            acc[h][1] = fmaf(v1, w, acc[h][1]);
            acc[h][2] = fmaf(v2, w, acc[h][2]);
            acc[h][3] = fmaf(v3, w, acc[h][3]);
        }
    }
    #pragma unroll
    for (int h = 0; h < 8; h++)
        #pragma unroll
        for (int j = 0; j < 4; j++) {
            float a = acc[h][j];
            #pragma unroll
            for (int off = 16; off; off >>= 1)
                a += __shfl_xor_sync(0xffffffffu, a, off);
            acc[h][j] = a;
        }
    if (lane == 0) {
        #pragma unroll
        for (int h = 0; h < 8; h++) {
            float bhv = bh[h0 + h];
            #pragma unroll
            for (int j = 0; j < 4; j++)
                g_has[(b0 + j) * Hnum + h0 + h] = acc[h][j] + bhv;
        }
    }
}

// ---------------------------------------------------------------------------
// Kernel B: softmax numerators with fused normalization.
// cp.async SMEM STAGING: in-flight data lives in shared memory, not
// registers -> ~128 lines in flight per block continuously, x5-6 blocks/SM
// >> the ~200 lines/SM the BW x latency product requires.
// Two 16KB stage buffers, depth-2 pipeline (compute stage s while s+1 loads).
// ---------------------------------------------------------------------------
__global__ __launch_bounds__(ETHR) void energy_kernel(
    const float* __restrict__ eo,
    const float* __restrict__ Wo,
    const int*   __restrict__ enc_len_w,
    float* __restrict__ out)
{
    const int b = blockIdx.y;
    const int chunk = blockIdx.x;
    const int tbase = chunk * CHUNK;
    // enc_len dtype auto-detect (JAX may canonicalize int64->int32):
    // lengths >= 1, so word[1]==0 iff buffer is little-endian int64.
    const bool is64 = (enc_len_w[1] == 0);
    const int len = is64 ? enc_len_w[2 * b] : enc_len_w[b];

    __shared__ __align__(16) float4 s_buf[2][STG_ROWS * ROW4];   // 2 x 16KB
    __shared__ __align__(16) float4 s_has[ROW4];                 // 2KB
    __shared__ __align__(16) float4 s_wo[ROW4];                  // 2KB
    __shared__ float s_ws[8];
    __shared__ float s_red[2];
    __shared__ float s_rinv;
    __shared__ int   s_last;

    const int tid  = threadIdx.x;
    const int warp = tid >> 5;
    const int lane = tid & 31;

    if (tbase < len) {
        if (tid < ROW4) {
            s_has[tid] = ((const float4*)(g_has + b * Hnum))[tid];
            s_wo[tid]  = ((const float4*)Wo)[tid];
        }
        // (visibility covered by the __syncthreads() after the first wait)

        const float4* __restrict__ eo4 = (const float4*)eo;

        // --- stage prefetch: 1024 float4 = 4 per thread, coalesced per row ---
        auto prefetch = [&](int s, int d) {
            #pragma unroll
            for (int q = 0; q < 4; q++) {
                const int flat = q * ETHR + tid;        // 0..1023
                const int row  = flat >> 7;             // 0..7
                const int col  = flat & (ROW4 - 1);     // 0..127
                const int t = tbase + s * STG_ROWS + row;
                if (t < len)
                    cp16(&s_buf[d][row * ROW4 + col],
                         &eo4[((size_t)t * Bnum + b) * ROW4 + col]);
            }
        };

        prefetch(0, 0);
        asm volatile("cp.async.commit_group;");
        prefetch(1, 1);
        asm volatile("cp.async.commit_group;");

        float wsum = 0.f;   // lane0 of each warp accumulates its rows
        #pragma unroll
        for (int s = 0; s < NSTG; s++) {
            asm volatile("cp.async.wait_group 1;");   // stage s resident
            __syncthreads();

            const int t = tbase + s * STG_ROWS + warp;   // warp w <- row w
            const float4* __restrict__ rowp = &s_buf[s & 1][warp * ROW4];
            float acc = 0.f;
            #pragma unroll
            for (int j = 0; j < 4; j++) {
                const int k = j * 32 + lane;
                float4 e  = rowp[k];
                float4 hs = s_has[k];
                float4 w  = s_wo[k];
                acc = fmaf(tanha(e.x + hs.x), w.x, acc);
                acc = fmaf(tanha(e.y + hs.y), w.y, acc);
                acc = fmaf(tanha(e.z + hs.z), w.z, acc);
                acc = fmaf(tanha(e.w + hs.w), w.w, acc);
            }
            #pragma unroll
            for (int off = 16; off; off >>= 1)
                acc += __shfl_xor_sync(0xffffffffu, acc, off);
            if (lane == 0) {
                // no-max exp is safe: |energy| <= sum|Wo| ~ 18 << fp32 range
                float p = (t < len) ? ex2a(acc * LOG2E) : 0.f;
                g_p[b * Tnum + t] = p;
                wsum += p;
            }
            __syncthreads();   // all warps done with buf[s&1] before refill

            if (s + 2 < NSTG) prefetch(s + 2, s & 1);
            asm volatile("cp.async.commit_group;");   // unconditional: keeps
        }                                             // wait_group counts aligned

        if (lane == 0) s_ws[warp] = wsum;
        __syncthreads();
        if (tid == 0) {
            float tot = 0.f;
            #pragma unroll
            for (int i = 0; i < 8; i++) tot += s_ws[i];
            g_psum[b * NCHUNK + chunk] = tot;
        }
    } else {
        // fully masked chunk: zeros, no eo traffic
        if (tid < CHUNK / 4)
            ((float4*)&g_p[b * Tnum + tbase])[tid] = make_float4(0.f, 0.f, 0.f, 0.f);
        if (tid == 0) g_psum[b * NCHUNK + chunk] = 0.f;
    }

    // ---- threadfence-reduction handoff: last block of this b normalizes ----
    __threadfence();
    if (tid == 0)
        s_last = (atomicAdd(&g_done[b], 1u) == NCHUNK - 1);
    __syncthreads();
    if (!s_last) return;

    if (tid < 64) {
        float v = g_psum[b * NCHUNK + tid];   // 64 partials
        #pragma unroll
        for (int off = 16; off; off >>= 1)
            v += __shfl_xor_sync(0xffffffffu, v, off);
        if (lane == 0) s_red[tid >> 5] = v;
    }
    __syncthreads();
    if (tid == 0) s_rinv = 1.0f / (s_red[0] + s_red[1]);
    __syncthreads();
    const float rinv = s_rinv;

    const float4* __restrict__ p4 = (const float4*)&g_p[b * Tnum];
    float4* __restrict__ o4 = (float4*)&out[b * Tnum];
    #pragma unroll
    for (int i = tid; i < Tnum / 4; i += ETHR) {
        float4 p = p4[i];
        float4 o;
        o.x = p.x * rinv; o.y = p.y * rinv; o.z = p.z * rinv; o.w = p.w * rinv;
        o4[i] = o;
    }
    if (tid == 0) g_done[b] = 0u;   // reset for next graph replay
}

// ---------------------------------------------------------------------------
extern "C" void kernel_launch(void* const* d_in, const int* in_sizes, int n_in,
                              void* d_out, int out_size)
{
    const float* hidden  = (const float*)d_in[0];      // [L,B,H]
    const float* eo      = (const float*)d_in[1];      // [T,B,H]
    const int*   enc_len = (const int*)d_in[2];        // [B] int32/int64 (auto-detect)
    const float* Wh      = (const float*)d_in[3];      // [H,H]
    const float* bh      = (const float*)d_in[4];      // [H]
    const float* Wo      = (const float*)d_in[5];      // [1,H]
    // d_in[6] = bo: uniform additive constant -> cancels in softmax, unused.
    float* out = (float*)d_out;                         // [B,T,1]

    proj_kernel<<<Hnum / 8, 256>>>(hidden, Wh, bh);
    energy_kernel<<<dim3(NCHUNK, Bnum), ETHR>>>(eo, Wo, enc_len, out);
}

// round 13
// speedup vs baseline: 1.0168x; 1.0168x over previous
#include <cuda_runtime.h>
#include <cstdint>
#include <math.h>

#define Bnum 32
#define Tnum 2048
#define Hnum 512
#define CHUNK 32                    // t-rows per energy block
#define STG_ROWS 8                  // rows per TMA stage
#define NSTG (CHUNK / STG_ROWS)     // 4 stages
#define NCHUNK (Tnum / CHUNK)       // 64 chunks per b
#define ETHR 256                    // energy block threads (8 warps)
#define ROW4 (Hnum / 4)             // 128 float4 per row
#define ROW_BYTES (Hnum * 4)        // 2048 bytes per (t,b) row

// Scratch (static device arrays — allocation-free per harness rules)
__device__ __align__(16) float g_has[Bnum * Hnum];     // ha (unscaled)
__device__ __align__(16) float g_p[Bnum * Tnum];       // unnormalized numerators
__device__ __align__(16) float g_psum[Bnum * NCHUNK];  // per-(b,chunk) partials
__device__ unsigned g_done[Bnum];                      // zero-init; reset each use

__device__ __forceinline__ float ex2a(float x) {
    float y; asm("ex2.approx.f32 %0, %1;" : "=f"(y) : "f"(x)); return y;
}
__device__ __forceinline__ float tanha(float x) {
    float y; asm("tanh.approx.f32 %0, %1;" : "=f"(y) : "f"(x)); return y;
}
__device__ __forceinline__ unsigned smem_u32(const void* p) {
    return (unsigned)__cvta_generic_to_shared(p);
}
// 1D bulk async copy gmem->smem through the TMA path (UBLKCP), completion
// signaled on an mbarrier via complete_tx.
__device__ __forceinline__ void bulk_cp(unsigned sdst, const void* gsrc,
                                        unsigned bytes, unsigned mbar) {
    asm volatile(
        "cp.async.bulk.shared::cta.global.mbarrier::complete_tx::bytes "
        "[%0], [%1], %2, [%3];"
        :: "r"(sdst), "l"(gsrc), "r"(bytes), "r"(mbar) : "memory");
}
__device__ __forceinline__ void mbar_init(unsigned mbar, unsigned count) {
    asm volatile("mbarrier.init.shared.b64 [%0], %1;" :: "r"(mbar), "r"(count) : "memory");
}
__device__ __forceinline__ void mbar_expect_tx(unsigned mbar, unsigned bytes) {
    asm volatile("mbarrier.arrive.expect_tx.shared.b64 _, [%0], %1;"
                 :: "r"(mbar), "r"(bytes) : "memory");
}
__device__ __forceinline__ void mbar_wait(unsigned mbar, unsigned parity) {
    unsigned done;
    asm volatile(
        "{\n\t.reg .pred p;\n\t"
        "mbarrier.try_wait.parity.acquire.cta.shared::cta.b64 p, [%1], %2;\n\t"
        "selp.b32 %0, 1, 0, p;\n\t}"
        : "=r"(done) : "r"(mbar), "r"(parity) : "memory");
    if (!done) {
        asm volatile(
            "{\n\t.reg .pred P1;\n\t"
            "WL_%=:\n\t"
            "mbarrier.try_wait.parity.acquire.cta.shared::cta.b64 P1, [%0], %1, 0x989680;\n\t"
            "@P1 bra.uni WD_%=;\n\t"
            "bra.uni WL_%=;\n\t"
            "WD_%=:\n\t}"
            :: "r"(mbar), "r"(parity) : "memory");
    }
}

#define LOG2E 1.4426950408889634f

// ---------------------------------------------------------------------------
// Kernel A: ha[b,h] = sum_k mean_L(hidden)[b,k]*Wh[h,k] + bh[h].
// ---------------------------------------------------------------------------
__global__ __launch_bounds__(256) void proj_kernel(
    const float* __restrict__ hidden,
    const float* __restrict__ Wh,
    const float* __restrict__ bh)
{
    const int h0 = blockIdx.x * 8;
    __shared__ float s_w[8 * Hnum];   // 16KB
    {
        const float4* __restrict__ w4 = (const float4*)(Wh + (size_t)h0 * Hnum);
        for (int i = threadIdx.x; i < 8 * Hnum / 4; i += 256)
            ((float4*)s_w)[i] = w4[i];
    }
    __syncthreads();

    const int warp = threadIdx.x >> 5;
    const int lane = threadIdx.x & 31;
    const int b0 = warp * 4;
    const float* __restrict__ hA = hidden;                 // layer 0
    const float* __restrict__ hB = hidden + Bnum * Hnum;   // layer 1

    float acc[8][4];
    #pragma unroll
    for (int h = 0; h < 8; h++)
        #pragma unroll
        for (int j = 0; j < 4; j++) acc[h][j] = 0.f;

    #pragma unroll
    for (int k = lane; k < Hnum; k += 32) {
        float v0 = 0.5f * (hA[(b0 + 0) * Hnum + k] + hB[(b0 + 0) * Hnum + k]);
        float v1 = 0.5f * (hA[(b0 + 1) * Hnum + k] + hB[(b0 + 1) * Hnum + k]);
        float v2 = 0.5f * (hA[(b0 + 2) * Hnum + k] + hB[(b0 + 2) * Hnum + k]);
        float v3 = 0.5f * (hA[(b0 + 3) * Hnum + k] + hB[(b0 + 3) * Hnum + k]);
        #pragma unroll
        for (int h = 0; h < 8; h++) {
            float w = s_w[h * Hnum + k];
            acc[h][0] = fmaf(v0, w, acc[h][0]);
            acc[h][1] = fmaf(v1, w, acc[h][1]);
            acc[h][2] = fmaf(v2, w, acc[h][2]);
            acc[h][3] = fmaf(v3, w, acc[h][3]);
        }
    }
    #pragma unroll
    for (int h = 0; h < 8; h++)
        #pragma unroll
        for (int j = 0; j < 4; j++) {
            float a = acc[h][j];
            #pragma unroll
            for (int off = 16; off; off >>= 1)
                a += __shfl_xor_sync(0xffffffffu, a, off);
            acc[h][j] = a;
        }
    if (lane == 0) {
        #pragma unroll
        for (int h = 0; h < 8; h++) {
            float bhv = bh[h0 + h];
            #pragma unroll
            for (int j = 0; j < 4; j++)
                g_has[(b0 + j) * Hnum + h0 + h] = acc[h][j] + bhv;
        }
    }
}

// ---------------------------------------------------------------------------
// Kernel B: softmax numerators with fused normalization.
// TMA (cp.async.bulk/UBLKCP) staging: the eo stream goes through the TMA
// path, bypassing the per-SM L1tex LDG queue that capped every LDG-based
// variant at ~3.1 TB/s. Depth-2 pipeline, 8x2KB row copies per stage,
// mbarrier complete_tx with exact valid-row byte counts (ragged stages).
// ---------------------------------------------------------------------------
__global__ __launch_bounds__(ETHR) void energy_kernel(
    const float* __restrict__ eo,
    const float* __restrict__ Wo,
    const int*   __restrict__ enc_len_w,
    float* __restrict__ out)
{
    const int b = blockIdx.x;
    const int chunk = blockIdx.y;     // chunk-major bid: late blocks mostly dead
    const int tbase = chunk * CHUNK;
    // enc_len dtype auto-detect (JAX may canonicalize int64->int32):
    // lengths >= 1, so word[1]==0 iff buffer is little-endian int64.
    const bool is64 = (enc_len_w[1] == 0);
    const int len = is64 ? enc_len_w[2 * b] : enc_len_w[b];

    __shared__ __align__(16) float4 s_buf[2][STG_ROWS * ROW4];   // 2 x 16KB
    __shared__ __align__(16) float4 s_has[ROW4];                 // 2KB
    __shared__ __align__(16) float4 s_wo[ROW4];                  // 2KB
    __shared__ __align__(8) unsigned long long s_mbar[2];
    __shared__ float s_ws[8];
    __shared__ float s_red[2];
    __shared__ float s_rinv;
    __shared__ int   s_last;

    const int tid  = threadIdx.x;
    const int warp = tid >> 5;
    const int lane = tid & 31;

    if (tbase < len) {
        if (tid < ROW4) {
            s_has[tid] = ((const float4*)(g_has + b * Hnum))[tid];
            s_wo[tid]  = ((const float4*)Wo)[tid];
        }
        if (tid == 0) {
            mbar_init(smem_u32(&s_mbar[0]), 1);
            mbar_init(smem_u32(&s_mbar[1]), 1);
        }
        __syncthreads();
        asm volatile("fence.proxy.async.shared::cta;" ::: "memory");

        const int nlive = min(NSTG, (len - tbase + STG_ROWS - 1) / STG_ROWS);

        // issue stage s into buffer s&1: one expect_tx + up to 8 row copies
        auto issue = [&](int s) {
            const int st = tbase + s * STG_ROWS;
            const int nrows = min(STG_ROWS, len - st);
            const unsigned mbar = smem_u32(&s_mbar[s & 1]);
            mbar_expect_tx(mbar, (unsigned)(nrows * ROW_BYTES));
            #pragma unroll
            for (int r = 0; r < STG_ROWS; r++) {
                if (r < nrows)
                    bulk_cp(smem_u32(&s_buf[s & 1][r * ROW4]),
                            eo + ((size_t)(st + r) * Bnum + b) * Hnum,
                            ROW_BYTES, mbar);
            }
        };

        if (tid == 0) {
            issue(0);
            if (nlive > 1) issue(1);
        }

        float wsum = 0.f;   // lane0 of each warp accumulates its rows
        #pragma unroll
        for (int s = 0; s < NSTG; s++) {
            const int t = tbase + s * STG_ROWS + warp;   // warp w <- row w
            float p = 0.f;
            if (s < nlive) {
                mbar_wait(smem_u32(&s_mbar[s & 1]), (s >> 1) & 1);

                const float4* __restrict__ rowp = &s_buf[s & 1][warp * ROW4];
                float acc = 0.f;
                #pragma unroll
                for (int j = 0; j < 4; j++) {
                    const int k = j * 32 + lane;
                    float4 e  = rowp[k];
                    float4 hs = s_has[k];
                    float4 w  = s_wo[k];
                    acc = fmaf(tanha(e.x + hs.x), w.x, acc);
                    acc = fmaf(tanha(e.y + hs.y), w.y, acc);
                    acc = fmaf(tanha(e.z + hs.z), w.z, acc);
                    acc = fmaf(tanha(e.w + hs.w), w.w, acc);
                }
                #pragma unroll
                for (int off = 16; off; off >>= 1)
                    acc += __shfl_xor_sync(0xffffffffu, acc, off);
                // no-max exp is safe: |energy| <= sum|Wo| ~ 18 << fp32 range
                if (t < len) p = ex2a(acc * LOG2E);

                __syncthreads();   // all warps done with buf[s&1] before refill
                if (tid == 0 && s + 2 < nlive) issue(s + 2);
            }
            if (lane == 0) {
                g_p[b * Tnum + t] = p;
                wsum += p;
            }
        }

        if (lane == 0) s_ws[warp] = wsum;
        __syncthreads();
        if (tid == 0) {
            float tot = 0.f;
            #pragma unroll
            for (int i = 0; i < 8; i++) tot += s_ws[i];
            g_psum[b * NCHUNK + chunk] = tot;
        }
    } else {
        // fully masked chunk: zeros, no eo traffic
        if (tid < CHUNK / 4)
            ((float4*)&g_p[b * Tnum + tbase])[tid] = make_float4(0.f, 0.f, 0.f, 0.f);
        if (tid == 0) g_psum[b * NCHUNK + chunk] = 0.f;
    }

    // ---- threadfence-reduction handoff: last block of this b normalizes ----
    __threadfence();
    if (tid == 0)
        s_last = (atomicAdd(&g_done[b], 1u) == NCHUNK - 1);
    __syncthreads();
    if (!s_last) return;

    if (tid < 64) {
        float v = g_psum[b * NCHUNK + tid];   // 64 partials
        #pragma unroll
        for (int off = 16; off; off >>= 1)
            v += __shfl_xor_sync(0xffffffffu, v, off);
        if (lane == 0) s_red[tid >> 5] = v;
    }
    __syncthreads();
    if (tid == 0) s_rinv = 1.0f / (s_red[0] + s_red[1]);
    __syncthreads();
    const float rinv = s_rinv;

    const float4* __restrict__ p4 = (const float4*)&g_p[b * Tnum];
    float4* __restrict__ o4 = (float4*)&out[b * Tnum];
    #pragma unroll
    for (int i = tid; i < Tnum / 4; i += ETHR) {
        float4 p = p4[i];
        float4 o;
        o.x = p.x * rinv; o.y = p.y * rinv; o.z = p.z * rinv; o.w = p.w * rinv;
        o4[i] = o;
    }
    if (tid == 0) g_done[b] = 0u;   // reset for next graph replay
}

// ---------------------------------------------------------------------------
extern "C" void kernel_launch(void* const* d_in, const int* in_sizes, int n_in,
                              void* d_out, int out_size)
{
    const float* hidden  = (const float*)d_in[0];      // [L,B,H]
    const float* eo      = (const float*)d_in[1];      // [T,B,H]
    const int*   enc_len = (const int*)d_in[2];        // [B] int32/int64 (auto-detect)
    const float* Wh      = (const float*)d_in[3];      // [H,H]
    const float* bh      = (const float*)d_in[4];      // [H]
    const float* Wo      = (const float*)d_in[5];      // [1,H]
    // d_in[6] = bo: uniform additive constant -> cancels in softmax, unused.
    float* out = (float*)d_out;                         // [B,T,1]

    proj_kernel<<<Hnum / 8, 256>>>(hidden, Wh, bh);
    energy_kernel<<<dim3(Bnum, NCHUNK), ETHR>>>(eo, Wo, enc_len, out);
}

// round 14
// speedup vs baseline: 1.1027x; 1.0845x over previous
#include <cuda_runtime.h>
#include <cstdint>
#include <math.h>

#define Bnum 32
#define Tnum 2048
#define Hnum 512
#define CHUNK 32                    // t-rows per live chunk
#define NCHUNK (Tnum / CHUNK)       // 64 chunks per b (max)
#define ETHR 256                    // energy block threads (8 warps)
#define ROW4 (Hnum / 4)             // 128 float4 per row

// Scratch (static device arrays — allocation-free per harness rules)
__device__ __align__(16) float g_has[Bnum * Hnum];     // ha (unscaled)
__device__ __align__(16) float g_p[Bnum * Tnum];       // unnormalized numerators
__device__ __align__(16) float g_psum[Bnum * NCHUNK];  // per-(b,chunk) partials
__device__ unsigned g_done[Bnum];                      // zero-init; reset each use

__device__ __forceinline__ float ex2a(float x) {
    float y; asm("ex2.approx.f32 %0, %1;" : "=f"(y) : "f"(x)); return y;
}
__device__ __forceinline__ float tanha(float x) {
    float y; asm("tanh.approx.f32 %0, %1;" : "=f"(y) : "f"(x)); return y;
}

#define LOG2E 1.4426950408889634f

// ---------------------------------------------------------------------------
// Kernel A: ha[b,h] = sum_k mean_L(hidden)[b,k]*Wh[h,k] + bh[h].
// ---------------------------------------------------------------------------
__global__ __launch_bounds__(256) void proj_kernel(
    const float* __restrict__ hidden,
    const float* __restrict__ Wh,
    const float* __restrict__ bh)
{
    const int h0 = blockIdx.x * 8;
    __shared__ float s_w[8 * Hnum];   // 16KB
    {
        const float4* __restrict__ w4 = (const float4*)(Wh + (size_t)h0 * Hnum);
        for (int i = threadIdx.x; i < 8 * Hnum / 4; i += 256)
            ((float4*)s_w)[i] = w4[i];
    }
    __syncthreads();

    const int warp = threadIdx.x >> 5;
    const int lane = threadIdx.x & 31;
    const int b0 = warp * 4;
    const float* __restrict__ hA = hidden;                 // layer 0
    const float* __restrict__ hB = hidden + Bnum * Hnum;   // layer 1

    float acc[8][4];
    #pragma unroll
    for (int h = 0; h < 8; h++)
        #pragma unroll
        for (int j = 0; j < 4; j++) acc[h][j] = 0.f;

    #pragma unroll
    for (int k = lane; k < Hnum; k += 32) {
        float v0 = 0.5f * (hA[(b0 + 0) * Hnum + k] + hB[(b0 + 0) * Hnum + k]);
        float v1 = 0.5f * (hA[(b0 + 1) * Hnum + k] + hB[(b0 + 1) * Hnum + k]);
        float v2 = 0.5f * (hA[(b0 + 2) * Hnum + k] + hB[(b0 + 2) * Hnum + k]);
        float v3 = 0.5f * (hA[(b0 + 3) * Hnum + k] + hB[(b0 + 3) * Hnum + k]);
        #pragma unroll
        for (int h = 0; h < 8; h++) {
            float w = s_w[h * Hnum + k];
            acc[h][0] = fmaf(v0, w, acc[h][0]);
            acc[h][1] = fmaf(v1, w, acc[h][1]);
            acc[h][2] = fmaf(v2, w, acc[h][2]);
            acc[h][3] = fmaf(v3, w, acc[h][3]);
        }
    }
    #pragma unroll
    for (int h = 0; h < 8; h++)
        #pragma unroll
        for (int j = 0; j < 4; j++) {
            float a = acc[h][j];
            #pragma unroll
            for (int off = 16; off; off >>= 1)
                a += __shfl_xor_sync(0xffffffffu, a, off);
            acc[h][j] = a;
        }
    if (lane == 0) {
        #pragma unroll
        for (int h = 0; h < 8; h++) {
            float bhv = bh[h0 + h];
            #pragma unroll
            for (int j = 0; j < 4; j++)
                g_has[(b0 + j) * Hnum + h0 + h] = acc[h][j] + bhv;
        }
    }
}

// ---------------------------------------------------------------------------
// Kernel B: softmax numerators with fused normalization.
// DENSE LIVE-ONLY SCHEDULING: blockIdx.x = i-th live (b,chunk) pair, mapped
// device-side by a warp prefix-sum over ceil(len[b]/32). Dead blocks (i >=
// n_live) exit immediately, so live work stays at full SM concurrency to
// the very end -- removes the starved high-t tail that capped BW at 3.1TB/s.
// Masked-tail zeros are written by the per-b epilogue (no dead-block work).
// ---------------------------------------------------------------------------
__global__ __launch_bounds__(ETHR, 8) void energy_kernel(
    const float* __restrict__ eo,
    const float* __restrict__ Wo,
    const int*   __restrict__ enc_len_w,
    float* __restrict__ out)
{
    const int tid  = threadIdx.x;
    const int warp = tid >> 5;
    const int lane = tid & 31;

    // enc_len dtype auto-detect (JAX may canonicalize int64->int32):
    // lengths >= 1, so word[1]==0 iff buffer is little-endian int64.
    const bool is64 = (enc_len_w[1] == 0);

    // ---- per-warp dense work mapping (redundant across warps, L1-hot) ----
    const int len_l = is64 ? enc_len_w[2 * lane] : enc_len_w[lane];  // lane=b
    const int c_l = (len_l + CHUNK - 1) >> 5;       // live chunks for lane-b
    int p = c_l;                                    // inclusive prefix sum
    #pragma unroll
    for (int off = 1; off < 32; off <<= 1) {
        int n = __shfl_up_sync(0xffffffffu, p, off);
        if (lane >= off) p += n;
    }
    const int n_live = __shfl_sync(0xffffffffu, p, 31);
    const int i = blockIdx.x;
    if (i >= n_live) return;                        // dead block: retire now

    const unsigned m = __ballot_sync(0xffffffffu, p > i);
    const int b     = __ffs(m) - 1;
    const int chunk = i - (__shfl_sync(0xffffffffu, p, b) -
                           __shfl_sync(0xffffffffu, c_l, b));
    const int len   = __shfl_sync(0xffffffffu, len_l, b);
    const int cb    = __shfl_sync(0xffffffffu, c_l, b);
    const int tbase = chunk * CHUNK;

    __shared__ __align__(16) float s_has[Hnum];
    __shared__ __align__(16) float s_wo[Hnum];
    __shared__ float s_ws[8];
    __shared__ float s_red[2];
    __shared__ float s_rinv;
    __shared__ int   s_last;

    for (int k = tid; k < Hnum / 4; k += ETHR) {
        ((float4*)s_has)[k] = ((const float4*)(g_has + b * Hnum))[k];
        ((float4*)s_wo)[k]  = ((const float4*)Wo)[k];
    }
    __syncthreads();

    const float4* __restrict__ eo4 = (const float4*)eo;
    float wsum = 0.f;
    #pragma unroll
    for (int r = 0; r < CHUNK / 8; r++) {           // warp owns 4 rows
        const int t = tbase + warp * (CHUNK / 8) + r;
        if (t < len) {
            const size_t base = ((size_t)t * Bnum + b) * ROW4;
            float acc = 0.f;
            #pragma unroll
            for (int j = 0; j < 4; j++) {
                const int k = j * 32 + lane;
                float4 e  = __ldcs(&eo4[base + k]);
                float4 hs = ((const float4*)s_has)[k];
                float4 w  = ((const float4*)s_wo)[k];
                acc = fmaf(tanha(e.x + hs.x), w.x, acc);
                acc = fmaf(tanha(e.y + hs.y), w.y, acc);
                acc = fmaf(tanha(e.z + hs.z), w.z, acc);
                acc = fmaf(tanha(e.w + hs.w), w.w, acc);
            }
            #pragma unroll
            for (int off = 16; off; off >>= 1)
                acc += __shfl_xor_sync(0xffffffffu, acc, off);
            if (lane == 0) {
                // no-max exp is safe: |energy| <= sum|Wo| ~ 18 << fp32 range
                float pv = ex2a(acc * LOG2E);
                g_p[b * Tnum + t] = pv;
                wsum += pv;
            }
        }
    }
    if (lane == 0) s_ws[warp] = wsum;
    __syncthreads();
    if (tid == 0) {
        float tot = 0.f;
        #pragma unroll
        for (int k = 0; k < 8; k++) tot += s_ws[k];
        g_psum[b * NCHUNK + chunk] = tot;
    }

    // ---- threadfence-reduction handoff: last live block of b normalizes ----
    __threadfence();
    if (tid == 0)
        s_last = (atomicAdd(&g_done[b], 1u) == (unsigned)(cb - 1));
    __syncthreads();
    if (!s_last) return;

    if (tid < 64) {
        float v = (tid < cb) ? g_psum[b * NCHUNK + tid] : 0.f;
        #pragma unroll
        for (int off = 16; off; off >>= 1)
            v += __shfl_xor_sync(0xffffffffu, v, off);
        if (lane == 0) s_red[tid >> 5] = v;
    }
    __syncthreads();
    if (tid == 0) s_rinv = 1.0f / (s_red[0] + s_red[1]);
    __syncthreads();
    const float rinv = s_rinv;

    // out[b,t] = p*rinv for t<len, 0 otherwise (masked tail zeroed here)
    float4* __restrict__ o4 = (float4*)&out[b * Tnum];
    const float* __restrict__ prow = &g_p[b * Tnum];
    #pragma unroll
    for (int q = tid; q < Tnum / 4; q += ETHR) {
        const int t0 = q * 4;
        float4 o = make_float4(0.f, 0.f, 0.f, 0.f);
        if (t0 + 3 < len) {
            float4 pv = ((const float4*)prow)[q];
            o.x = pv.x * rinv; o.y = pv.y * rinv;
            o.z = pv.z * rinv; o.w = pv.w * rinv;
        } else if (t0 < len) {
            if (t0 + 0 < len) o.x = prow[t0 + 0] * rinv;
            if (t0 + 1 < len) o.y = prow[t0 + 1] * rinv;
            if (t0 + 2 < len) o.z = prow[t0 + 2] * rinv;
            if (t0 + 3 < len) o.w = prow[t0 + 3] * rinv;
        }
        o4[q] = o;
    }
    if (tid == 0) g_done[b] = 0u;   // reset for next graph replay
}

// ---------------------------------------------------------------------------
extern "C" void kernel_launch(void* const* d_in, const int* in_sizes, int n_in,
                              void* d_out, int out_size)
{
    const float* hidden  = (const float*)d_in[0];      // [L,B,H]
    const float* eo      = (const float*)d_in[1];      // [T,B,H]
    const int*   enc_len = (const int*)d_in[2];        // [B] int32/int64 (auto-detect)
    const float* Wh      = (const float*)d_in[3];      // [H,H]
    const float* bh      = (const float*)d_in[4];      // [H]
    const float* Wo      = (const float*)d_in[5];      // [1,H]
    // d_in[6] = bo: uniform additive constant -> cancels in softmax, unused.
    float* out = (float*)d_out;                         // [B,T,1]

    proj_kernel<<<Hnum / 8, 256>>>(hidden, Wh, bh);
    energy_kernel<<<Bnum * NCHUNK, ETHR>>>(eo, Wo, enc_len, out);
}